// round 7
// baseline (speedup 1.0000x reference)
#include <cuda_runtime.h>
#include <cuda_bf16.h>

#define FMAX 20908

// Repacked per-face record: 4 x float4 = 64B, 128B-aligned array so each
// record lies entirely within one 128B cache line.
// chunk0=(t00,t01,t02,t10) chunk1=(t11,t12,t20,t21) chunk2=(t22,n0,n1,n2) chunk3=pad
__device__ __align__(128) float4 g_face_pack[FMAX * 4];

// one thread per (face, chunk)
__global__ __launch_bounds__(256) void repack_kernel(
    const float* __restrict__ triangles,    // [F,3,3]
    const float* __restrict__ face_normals, // [F,3]
    int F)
{
    int i = blockIdx.x * blockDim.x + threadIdx.x;
    if (i >= F * 3) return;
    int f = i / 3;
    int c = i - 3 * f;
    const float* t = triangles + (size_t)f * 9;
    float4 v;
    if (c == 0)      v = make_float4(t[0], t[1], t[2], t[3]);
    else if (c == 1) v = make_float4(t[4], t[5], t[6], t[7]);
    else {
        const float* n = face_normals + (size_t)f * 3;
        v = make_float4(t[8], n[0], n[1], n[2]);
    }
    g_face_pack[4*f + c] = v;
}

// pick component c (0..2) from (a0,a1,a2)
__device__ __forceinline__ float sel3(int c, float a0, float a1, float a2) {
    return (c == 0) ? a0 : ((c == 1) ? a1 : a2);
}

__global__ __launch_bounds__(256) void sd_coop_kernel(
    const float* __restrict__ points,        // [Q,3]
    const int*   __restrict__ closest_faces, // [Q]
    const float* __restrict__ closest_bcs,   // [Q,3]
    float* __restrict__ out,
    int Q)
{
    __shared__ float4 s_face[8 * 32 * 3];   // 12 KB, 48B record stride

    int tid  = threadIdx.x;
    int lane = tid & 31;
    int wrp  = tid >> 5;
    int q    = blockIdx.x * blockDim.x + tid;

    int wb = q - lane;                      // warp's first point
    if (wb >= Q) return;
    bool full_warp = (wb + 32 <= Q);
    bool active = (q < Q);
    int qe = active ? q : (Q - 1);

    int f = closest_faces[qe];

    // ---- streaming loads ----
    float p0, p1, p2, c0, c1, c2;
    if (full_warp) {
        // dense cooperative reads (1 wavefront per instruction) + shfl transpose
        const float* pbase = points + (size_t)3 * wb;
        float d0 = pbase[lane];
        float d1 = pbase[32 + lane];
        float d2 = pbase[64 + lane];
        const float* bbase = closest_bcs + (size_t)3 * wb;
        float e0 = bbase[lane];
        float e1 = bbase[32 + lane];
        float e2 = bbase[64 + lane];

        #pragma unroll
        for (int i = 0; i < 3; i++) {
            int idx = 3 * lane + i;        // flat element this lane wants
            int m = idx >> 5;              // which dense register
            int s = idx & 31;              // source lane
            float a0 = __shfl_sync(0xffffffffu, d0, s);
            float a1 = __shfl_sync(0xffffffffu, d1, s);
            float a2 = __shfl_sync(0xffffffffu, d2, s);
            float pv = sel3(m, a0, a1, a2);
            float b0s = __shfl_sync(0xffffffffu, e0, s);
            float b1s = __shfl_sync(0xffffffffu, e1, s);
            float b2s = __shfl_sync(0xffffffffu, e2, s);
            float bv = sel3(m, b0s, b1s, b2s);
            if (i == 0) { p0 = pv; c0 = bv; }
            else if (i == 1) { p1 = pv; c1 = bv; }
            else { p2 = pv; c2 = bv; }
        }
    } else {
        p0 = points[3*qe+0]; p1 = points[3*qe+1]; p2 = points[3*qe+2];
        c0 = closest_bcs[3*qe+0]; c1 = closest_bcs[3*qe+1]; c2 = closest_bcs[3*qe+2];
    }

    // ---- warp-cooperative gather (1 wavefront per point) ----
    float4* sw = s_face + wrp * 96;
    int c = lane & 3;
    int pgrp = lane >> 2;
    #pragma unroll
    for (int r = 0; r < 4; r++) {
        int p_local = 8*r + pgrp;
        int fp = __shfl_sync(0xffffffffu, f, p_local);
        if (c < 3) {
            float4 v = __ldg(&g_face_pack[4*(size_t)fp + c]);
            sw[p_local * 3 + c] = v;
        }
    }
    __syncwarp();

    float4 v0 = sw[lane*3 + 0];
    float4 v1 = sw[lane*3 + 1];
    float4 v2 = sw[lane*3 + 2];

    // ---- compute ----
    float b0 = fminf(fmaxf(c0, 0.0f), 1.0f);
    float b1 = fminf(fmaxf(c1, 0.0f), 1.0f);
    float b2 = fminf(fmaxf(c2, 0.0f), 1.0f);

    float cpx = fmaf(v0.x, b0, fmaf(v0.w, b1, v1.z * b2));
    float cpy = fmaf(v0.y, b0, fmaf(v1.x, b1, v1.w * b2));
    float cpz = fmaf(v0.z, b0, fmaf(v1.y, b1, v2.x * b2));

    float r0 = cpx - p0;
    float r1 = cpy - p1;
    float r2 = cpz - p2;

    float sq   = fmaf(r0, r0, fmaf(r1, r1, r2 * r2));
    float dist = sqrtf(sq);
    float inv  = (dist == 0.0f) ? 1.0f : (1.0f / dist);

    float rn0 = r0 * inv;
    float rn1 = r1 * inv;
    float rn2 = r2 * inv;

    float dot  = fmaf(r0, v2.y, fmaf(r1, v2.z, r2 * v2.w));
    float sign = (dot > 0.0f) ? -1.0f : 1.0f;
    float sd   = sign * dist;

    float* rn_out = out + (size_t)Q;
    float* cp_out = out + (size_t)4 * Q;
    float* cf_out = out + (size_t)7 * Q;
    float* bc_out = out + (size_t)8 * Q;

    if (full_warp) {
        out[q] = sd;
        cf_out[q] = (float)f;

        // dense shfl-transposed stores for the 3-wide sections
        float* rn_sec = rn_out + (size_t)3 * wb;
        float* cp_sec = cp_out + (size_t)3 * wb;
        float* bc_sec = bc_out + (size_t)3 * wb;
        #pragma unroll
        for (int k = 0; k < 3; k++) {
            int idx = 32*k + lane;         // flat element this lane stores
            int s = idx / 3;               // source lane (point owner)
            int cc = idx - 3*s;            // component
            float a0 = __shfl_sync(0xffffffffu, rn0, s);
            float a1 = __shfl_sync(0xffffffffu, rn1, s);
            float a2 = __shfl_sync(0xffffffffu, rn2, s);
            rn_sec[idx] = sel3(cc, a0, a1, a2);
            float u0 = __shfl_sync(0xffffffffu, cpx, s);
            float u1 = __shfl_sync(0xffffffffu, cpy, s);
            float u2 = __shfl_sync(0xffffffffu, cpz, s);
            cp_sec[idx] = sel3(cc, u0, u1, u2);
            float w0 = __shfl_sync(0xffffffffu, b0, s);
            float w1 = __shfl_sync(0xffffffffu, b1, s);
            float w2 = __shfl_sync(0xffffffffu, b2, s);
            bc_sec[idx] = sel3(cc, w0, w1, w2);
        }
    } else if (active) {
        out[q] = sd;
        cf_out[q] = (float)f;
        rn_out[3*q+0] = rn0; rn_out[3*q+1] = rn1; rn_out[3*q+2] = rn2;
        cp_out[3*q+0] = cpx; cp_out[3*q+1] = cpy; cp_out[3*q+2] = cpz;
        bc_out[3*q+0] = b0;  bc_out[3*q+1] = b1;  bc_out[3*q+2] = b2;
    }
}

extern "C" void kernel_launch(void* const* d_in, const int* in_sizes, int n_in,
                              void* d_out, int out_size) {
    const float* triangles     = (const float*)d_in[0];
    const float* face_normals  = (const float*)d_in[1];
    const float* points        = (const float*)d_in[2];
    const int*   closest_faces = (const int*)d_in[3];
    const float* closest_bcs   = (const float*)d_in[4];
    float* out = (float*)d_out;

    int F = in_sizes[0] / 9;
    int Q = in_sizes[3];

    int Fc = F > FMAX ? FMAX : F;
    repack_kernel<<<(Fc * 3 + 255) / 256, 256>>>(triangles, face_normals, Fc);

    int blocks = (Q + 255) / 256;
    sd_coop_kernel<<<blocks, 256>>>(points, closest_faces, closest_bcs, out, Q);
}

// round 8
// speedup vs baseline: 1.5057x; 1.5057x over previous
#include <cuda_runtime.h>
#include <cuda_bf16.h>

#define FMAX 20908

// Repacked per-face record: 4 x float4 = 64B, 128B-aligned array so each
// record lies entirely within one 128B cache line.
// chunk0=(t00,t01,t02,t10) chunk1=(t11,t12,t20,t21) chunk2=(t22,n0,n1,n2) chunk3=pad
__device__ __align__(128) float4 g_face_pack[FMAX * 4];

// one thread per (face, chunk)
__global__ __launch_bounds__(256) void repack_kernel(
    const float* __restrict__ triangles,    // [F,3,3]
    const float* __restrict__ face_normals, // [F,3]
    int F)
{
    int i = blockIdx.x * blockDim.x + threadIdx.x;
    if (i >= F * 3) return;
    int f = i / 3;
    int c = i - 3 * f;
    const float* t = triangles + (size_t)f * 9;
    float4 v;
    if (c == 0)      v = make_float4(t[0], t[1], t[2], t[3]);
    else if (c == 1) v = make_float4(t[4], t[5], t[6], t[7]);
    else {
        const float* n = face_normals + (size_t)f * 3;
        v = make_float4(t[8], n[0], n[1], n[2]);
    }
    g_face_pack[4*f + c] = v;
}

// 256 threads = 8 warps; each THREAD computes TWO points (two 256-point
// slabs per block) for doubled memory-level parallelism per warp.
// Gather is warp-cooperative: one LDG.128 fetches chunks of 8 different
// 64B-aligned records (1 L1 wavefront per point).
__global__ __launch_bounds__(256) void sd_coop2_kernel(
    const float* __restrict__ points,        // [Q,3]
    const int*   __restrict__ closest_faces, // [Q]
    const float* __restrict__ closest_bcs,   // [Q,3]
    float* __restrict__ out,
    int Q)
{
    // staging: 2 slabs x 8 warps x 32 points x 3 float4 (48B record stride,
    // stride/16 odd -> conflict-free LDS.128)
    __shared__ float4 s_face[2 * 8 * 32 * 3];   // 24 KB

    int tid  = threadIdx.x;
    int lane = tid & 31;
    int wrp  = tid >> 5;
    int base = blockIdx.x * 512;

    int  q[2];
    bool act[2];
    int  qe[2];
    int  f[2];
    q[0] = base + tid;
    q[1] = base + 256 + tid;

    #pragma unroll
    for (int s = 0; s < 2; s++) {
        act[s] = (q[s] < Q);
        qe[s]  = act[s] ? q[s] : (Q - 1);
        f[s]   = closest_faces[qe[s]];
    }

    // ---- warp-cooperative gathers (both slabs in flight together) ----
    int c    = lane & 3;                  // chunk id (3 = idle lane)
    int pgrp = lane >> 2;                 // point sub-index 0..7
    #pragma unroll
    for (int s = 0; s < 2; s++) {
        int wb = q[s] - lane;
        if (wb >= Q) continue;            // uniform per warp
        float4* sw = s_face + (size_t)(s * 8 + wrp) * 96;
        #pragma unroll
        for (int r = 0; r < 4; r++) {
            int p_local = 8*r + pgrp;
            int fp = __shfl_sync(0xffffffffu, f[s], p_local);
            if (c < 3) {
                float4 v = __ldg(&g_face_pack[4*(size_t)fp + c]);
                sw[p_local * 3 + c] = v;
            }
        }
    }

    // ---- streaming loads (overlap gather latency) ----
    float p0[2], p1[2], p2[2], c0[2], c1[2], c2[2];
    #pragma unroll
    for (int s = 0; s < 2; s++) {
        int e = qe[s];
        c0[s] = closest_bcs[3*e + 0];
        c1[s] = closest_bcs[3*e + 1];
        c2[s] = closest_bcs[3*e + 2];
        p0[s] = points[3*e + 0];
        p1[s] = points[3*e + 1];
        p2[s] = points[3*e + 2];
    }

    __syncwarp();

    float* rn_out = out + (size_t)Q;
    float* cp_out = out + (size_t)4 * Q;
    float* cf_out = out + (size_t)7 * Q;
    float* bc_out = out + (size_t)8 * Q;

    #pragma unroll
    for (int s = 0; s < 2; s++) {
        if (!act[s]) continue;
        const float4* sw = s_face + (size_t)(s * 8 + wrp) * 96;
        float4 v0 = sw[lane*3 + 0];
        float4 v1 = sw[lane*3 + 1];
        float4 v2 = sw[lane*3 + 2];

        float b0 = fminf(fmaxf(c0[s], 0.0f), 1.0f);
        float b1 = fminf(fmaxf(c1[s], 0.0f), 1.0f);
        float b2 = fminf(fmaxf(c2[s], 0.0f), 1.0f);

        // v0=(t00,t01,t02,t10) v1=(t11,t12,t20,t21) v2=(t22,n0,n1,n2)
        float cpx = fmaf(v0.x, b0, fmaf(v0.w, b1, v1.z * b2));
        float cpy = fmaf(v0.y, b0, fmaf(v1.x, b1, v1.w * b2));
        float cpz = fmaf(v0.z, b0, fmaf(v1.y, b1, v2.x * b2));

        float r0 = cpx - p0[s];
        float r1 = cpy - p1[s];
        float r2 = cpz - p2[s];

        float sq   = fmaf(r0, r0, fmaf(r1, r1, r2 * r2));
        float dist = sqrtf(sq);
        float inv  = (dist == 0.0f) ? 1.0f : (1.0f / dist);

        float rn0 = r0 * inv;
        float rn1 = r1 * inv;
        float rn2 = r2 * inv;

        float dot  = fmaf(r0, v2.y, fmaf(r1, v2.z, r2 * v2.w));
        float sign = (dot > 0.0f) ? -1.0f : 1.0f;

        int qq = q[s];
        out[qq]    = sign * dist;
        cf_out[qq] = (float)f[s];
        rn_out[3*qq+0] = rn0; rn_out[3*qq+1] = rn1; rn_out[3*qq+2] = rn2;
        cp_out[3*qq+0] = cpx; cp_out[3*qq+1] = cpy; cp_out[3*qq+2] = cpz;
        bc_out[3*qq+0] = b0;  bc_out[3*qq+1] = b1;  bc_out[3*qq+2] = b2;
    }
}

extern "C" void kernel_launch(void* const* d_in, const int* in_sizes, int n_in,
                              void* d_out, int out_size) {
    const float* triangles     = (const float*)d_in[0];
    const float* face_normals  = (const float*)d_in[1];
    const float* points        = (const float*)d_in[2];
    const int*   closest_faces = (const int*)d_in[3];
    const float* closest_bcs   = (const float*)d_in[4];
    float* out = (float*)d_out;

    int F = in_sizes[0] / 9;
    int Q = in_sizes[3];

    int Fc = F > FMAX ? FMAX : F;
    repack_kernel<<<(Fc * 3 + 255) / 256, 256>>>(triangles, face_normals, Fc);

    int blocks = (Q + 511) / 512;
    sd_coop2_kernel<<<blocks, 256>>>(points, closest_faces, closest_bcs, out, Q);
}

// round 9
// speedup vs baseline: 1.5807x; 1.0498x over previous
#include <cuda_runtime.h>
#include <cuda_bf16.h>

#define FMAX 20908

// Repacked per-face record: 4 x float4 = 64B, 128B-aligned array so each
// record lies entirely within one 128B cache line.
// chunk0=(t00,t01,t02,t10) chunk1=(t11,t12,t20,t21) chunk2=(t22,n0,n1,n2) chunk3=pad
__device__ __align__(128) float4 g_face_pack[FMAX * 4];

// one thread per (face, chunk)
__global__ __launch_bounds__(256) void repack_kernel(
    const float* __restrict__ triangles,    // [F,3,3]
    const float* __restrict__ face_normals, // [F,3]
    int F)
{
    int i = blockIdx.x * blockDim.x + threadIdx.x;
    if (i >= F * 3) return;
    int f = i / 3;
    int c = i - 3 * f;
    const float* t = triangles + (size_t)f * 9;
    float4 v;
    if (c == 0)      v = make_float4(t[0], t[1], t[2], t[3]);
    else if (c == 1) v = make_float4(t[4], t[5], t[6], t[7]);
    else {
        const float* n = face_normals + (size_t)f * 3;
        v = make_float4(t[8], n[0], n[1], n[2]);
    }
    g_face_pack[4*f + c] = v;
}

// 128 threads = 4 warps; each THREAD computes TWO points (two 128-point
// slabs per block). Small CTA keeps smem at 12KB and the reg limit high,
// so we get ~75% occupancy AND doubled per-warp MLP.
// Gather is warp-cooperative: one LDG.128 fetches chunks of 8 different
// 64B-aligned records (1 L1 wavefront per point).
__global__ __launch_bounds__(128) void sd_coop2_kernel(
    const float* __restrict__ points,        // [Q,3]
    const int*   __restrict__ closest_faces, // [Q]
    const float* __restrict__ closest_bcs,   // [Q,3]
    float* __restrict__ out,
    int Q)
{
    // staging: 2 slabs x 4 warps x 32 points x 3 float4 (48B record stride,
    // stride/16 odd -> conflict-free LDS.128)
    __shared__ float4 s_face[2 * 4 * 32 * 3];   // 12 KB

    int tid  = threadIdx.x;
    int lane = tid & 31;
    int wrp  = tid >> 5;
    int base = blockIdx.x * 256;

    int  q[2];
    bool act[2];
    int  qe[2];
    int  f[2];
    q[0] = base + tid;
    q[1] = base + 128 + tid;

    #pragma unroll
    for (int s = 0; s < 2; s++) {
        act[s] = (q[s] < Q);
        qe[s]  = act[s] ? q[s] : (Q - 1);
        f[s]   = closest_faces[qe[s]];
    }

    // ---- warp-cooperative gathers (both slabs in flight together) ----
    int c    = lane & 3;                  // chunk id (3 = idle lane)
    int pgrp = lane >> 2;                 // point sub-index 0..7
    #pragma unroll
    for (int s = 0; s < 2; s++) {
        int wb = q[s] - lane;
        if (wb >= Q) continue;            // uniform per warp
        float4* sw = s_face + (size_t)(s * 4 + wrp) * 96;
        #pragma unroll
        for (int r = 0; r < 4; r++) {
            int p_local = 8*r + pgrp;
            int fp = __shfl_sync(0xffffffffu, f[s], p_local);
            if (c < 3) {
                float4 v = __ldg(&g_face_pack[4*(size_t)fp + c]);
                sw[p_local * 3 + c] = v;
            }
        }
    }

    // ---- streaming loads (overlap gather latency) ----
    float p0[2], p1[2], p2[2], c0[2], c1[2], c2[2];
    #pragma unroll
    for (int s = 0; s < 2; s++) {
        int e = qe[s];
        c0[s] = closest_bcs[3*e + 0];
        c1[s] = closest_bcs[3*e + 1];
        c2[s] = closest_bcs[3*e + 2];
        p0[s] = points[3*e + 0];
        p1[s] = points[3*e + 1];
        p2[s] = points[3*e + 2];
    }

    __syncwarp();

    float* rn_out = out + (size_t)Q;
    float* cp_out = out + (size_t)4 * Q;
    float* cf_out = out + (size_t)7 * Q;
    float* bc_out = out + (size_t)8 * Q;

    #pragma unroll
    for (int s = 0; s < 2; s++) {
        if (!act[s]) continue;
        const float4* sw = s_face + (size_t)(s * 4 + wrp) * 96;
        float4 v0 = sw[lane*3 + 0];
        float4 v1 = sw[lane*3 + 1];
        float4 v2 = sw[lane*3 + 2];

        float b0 = fminf(fmaxf(c0[s], 0.0f), 1.0f);
        float b1 = fminf(fmaxf(c1[s], 0.0f), 1.0f);
        float b2 = fminf(fmaxf(c2[s], 0.0f), 1.0f);

        // v0=(t00,t01,t02,t10) v1=(t11,t12,t20,t21) v2=(t22,n0,n1,n2)
        float cpx = fmaf(v0.x, b0, fmaf(v0.w, b1, v1.z * b2));
        float cpy = fmaf(v0.y, b0, fmaf(v1.x, b1, v1.w * b2));
        float cpz = fmaf(v0.z, b0, fmaf(v1.y, b1, v2.x * b2));

        float r0 = cpx - p0[s];
        float r1 = cpy - p1[s];
        float r2 = cpz - p2[s];

        float sq   = fmaf(r0, r0, fmaf(r1, r1, r2 * r2));
        float dist = sqrtf(sq);
        float inv  = (dist == 0.0f) ? 1.0f : (1.0f / dist);

        float rn0 = r0 * inv;
        float rn1 = r1 * inv;
        float rn2 = r2 * inv;

        float dot  = fmaf(r0, v2.y, fmaf(r1, v2.z, r2 * v2.w));
        float sign = (dot > 0.0f) ? -1.0f : 1.0f;

        int qq = q[s];
        out[qq]    = sign * dist;
        cf_out[qq] = (float)f[s];
        rn_out[3*qq+0] = rn0; rn_out[3*qq+1] = rn1; rn_out[3*qq+2] = rn2;
        cp_out[3*qq+0] = cpx; cp_out[3*qq+1] = cpy; cp_out[3*qq+2] = cpz;
        bc_out[3*qq+0] = b0;  bc_out[3*qq+1] = b1;  bc_out[3*qq+2] = b2;
    }
}

extern "C" void kernel_launch(void* const* d_in, const int* in_sizes, int n_in,
                              void* d_out, int out_size) {
    const float* triangles     = (const float*)d_in[0];
    const float* face_normals  = (const float*)d_in[1];
    const float* points        = (const float*)d_in[2];
    const int*   closest_faces = (const int*)d_in[3];
    const float* closest_bcs   = (const float*)d_in[4];
    float* out = (float*)d_out;

    int F = in_sizes[0] / 9;
    int Q = in_sizes[3];

    int Fc = F > FMAX ? FMAX : F;
    repack_kernel<<<(Fc * 3 + 255) / 256, 256>>>(triangles, face_normals, Fc);

    int blocks = (Q + 255) / 256;
    sd_coop2_kernel<<<blocks, 128>>>(points, closest_faces, closest_bcs, out, Q);
}